// round 5
// baseline (speedup 1.0000x reference)
#include <cuda_runtime.h>

// GC_3D loss: BCE(mean) + 1 - (1/13) * sum_k [ sum(di_k*dt_k) / (sum(dt_k^2)+1e-5) ]
// Shape (4,1,128,192,192) f32, forward-z canonical offsets.
// R5: R3 memory structure (scalar 6-float windows, register z-march) with
//     f32x2 packed math built transiently at consumption (no persistent pairs).

#define DX 192
#define DY 192
#define DZ 128
#define DXY (DX * DY)
#define NX4 48
#define NSUM 27
#define ZCHUNKS 4
#define ZSTEP (DZ / ZCHUNKS)   // 32

typedef unsigned long long u64;

__device__ double g_sums[NSUM];

__global__ void gc3d_zero_kernel() {
    int i = threadIdx.x;
    if (i < NSUM) g_sums[i] = 0.0;
}

// ---- packed f32x2 primitives ----
__device__ __forceinline__ u64 pk2(float lo, float hi) {
    u64 r; asm("mov.b64 %0,{%1,%2};" : "=l"(r) : "f"(lo), "f"(hi)); return r;
}
__device__ __forceinline__ void upk(u64 v, float& lo, float& hi) {
    asm("mov.b64 {%0,%1},%2;" : "=f"(lo), "=f"(hi) : "l"(v));
}
__device__ __forceinline__ u64 fma2(u64 a, u64 b, u64 c) {
    u64 r; asm("fma.rn.f32x2 %0,%1,%2,%3;" : "=l"(r) : "l"(a), "l"(b), "l"(c)); return r;
}
__device__ __forceinline__ u64 mul2(u64 a, u64 b) {
    u64 r; asm("mul.rn.f32x2 %0,%1,%2;" : "=l"(r) : "l"(a), "l"(b)); return r;
}
#define NEG1 0xBF800000BF800000ULL
// a - b == fma(b, -1, a)  (single rounding)
__device__ __forceinline__ u64 sub2(u64 a, u64 b) { return fma2(b, NEG1, a); }

__device__ __forceinline__ void ldwin(const float* __restrict__ p,
                                      int o_m1, int o_p4, float w[6]) {
    float4 v = *reinterpret_cast<const float4*>(p);
    w[0] = __ldg(p + o_m1);
    w[1] = v.x; w[2] = v.y; w[3] = v.z; w[4] = v.w;
    w[5] = __ldg(p + o_p4);
}

// One (row,dx) offset over 4 voxels as two packed pairs.
// MA/MB: guard-multiply dt of low/high pair.
template<bool MA, bool MB>
__device__ __forceinline__ void acc2(u64 nIa, u64 nIb, u64 nTa, u64 nTb,
                                     u64 cIa, u64 cIb, u64 cTa, u64 cTb,
                                     u64 Ga, u64 Gb, u64& D, u64& Q)
{
    u64 dia = sub2(nIa, cIa), dib = sub2(nIb, cIb);
    u64 dta = sub2(nTa, cTa), dtb = sub2(nTb, cTb);
    if (MA) dta = mul2(dta, Ga);
    if (MB) dtb = mul2(dtb, Gb);
    D = fma2(dia, dta, D); D = fma2(dib, dtb, D);
    Q = fma2(dta, dta, Q); Q = fma2(dtb, dtb, Q);
}

// Three dx offsets on one scalar row window; pairs built transiently.
template<bool GY>
__device__ __forceinline__ void row3p(const float Wi[6], const float Wt[6],
                                      u64 cIa, u64 cIb, u64 cTa, u64 cTb,
                                      u64 gA0, u64 gB0, u64 gB2,
                                      u64* dot, u64* den, int K)
{
    const u64 i01 = pk2(Wi[0], Wi[1]), i12 = pk2(Wi[1], Wi[2]);
    const u64 i23 = pk2(Wi[2], Wi[3]), i34 = pk2(Wi[3], Wi[4]);
    const u64 i45 = pk2(Wi[4], Wi[5]);
    const u64 t01 = pk2(Wt[0], Wt[1]), t12 = pk2(Wt[1], Wt[2]);
    const u64 t23 = pk2(Wt[2], Wt[3]), t34 = pk2(Wt[3], Wt[4]);
    const u64 t45 = pk2(Wt[4], Wt[5]);
    acc2<true, GY >(i01, i23, t01, t23, cIa, cIb, cTa, cTb, gA0, gB0, dot[K],     den[K]);
    acc2<GY,   GY >(i12, i34, t12, t34, cIa, cIb, cTa, cTb, gB0, gB0, dot[K + 1], den[K + 1]);
    acc2<GY,   true>(i23, i45, t23, t45, cIa, cIb, cTa, cTb, gB0, gB2, dot[K + 2], den[K + 2]);
}

// BCE in log2 domain on the 4 scalar centers
#define BCE4(CI, CT) do {                                                   \
    float l1, l2;                                                           \
    l1 = __log2f(CI[1]); l2 = __log2f(1.0f - CI[1]); bce += l2 + CT[1]*(l1-l2); \
    l1 = __log2f(CI[2]); l2 = __log2f(1.0f - CI[2]); bce += l2 + CT[2]*(l1-l2); \
    l1 = __log2f(CI[3]); l2 = __log2f(1.0f - CI[3]); bce += l2 + CT[3]*(l1-l2); \
    l1 = __log2f(CI[4]); l2 = __log2f(1.0f - CI[4]); bce += l2 + CT[4]*(l1-l2); \
} while (0)

template<bool YG>
__device__ __forceinline__ void gc3d_march(
    const float* __restrict__ in, const float* __restrict__ tg,
    int base, int nsteps, bool do_epi,
    int o_m1, int o_p4, int dUp, int dDn,
    float fxm, float fxp, float fym, float fyp,
    u64* dot, u64* den, float& bce)
{
    const u64 gxm = pk2(fxm, 1.0f);
    const u64 gxp = pk2(1.0f, fxp);
    const u64 gpA0 = pk2(fxm * fyp, fyp), gpB0 = pk2(fyp, fyp), gpB2 = pk2(fyp, fxp * fyp);
    const u64 gmA0 = pk2(fxm * fym, fym), gmB0 = pk2(fym, fym), gmB2 = pk2(fym, fxp * fym);

    float CWi[6], CWt[6], UWi[6], UWt[6];      // carried: center row, y+1 row
    ldwin(in + base,       o_m1, o_p4, CWi);
    ldwin(tg + base,       o_m1, o_p4, CWt);
    ldwin(in + base + dUp, o_m1, o_p4, UWi);
    ldwin(tg + base + dUp, o_m1, o_p4, UWt);

#pragma unroll 2
    for (int s = 0; s < nsteps; ++s) {
        const int baseN = base + DXY;
        float NmI[6], NmT[6], NcI[6], NcT[6], NpI[6], NpT[6];
        ldwin(in + baseN + dDn, o_m1, o_p4, NmI);
        ldwin(tg + baseN + dDn, o_m1, o_p4, NmT);
        ldwin(in + baseN,       o_m1, o_p4, NcI);
        ldwin(tg + baseN,       o_m1, o_p4, NcT);
        ldwin(in + baseN + dUp, o_m1, o_p4, NpI);
        ldwin(tg + baseN + dUp, o_m1, o_p4, NpT);

        const u64 cIa = pk2(CWi[1], CWi[2]), cIb = pk2(CWi[3], CWi[4]);
        const u64 cTa = pk2(CWt[1], CWt[2]), cTb = pk2(CWt[3], CWt[4]);

        BCE4(CWi, CWt);

        // k0: (0,0,+1) on center row (pairs (w2,w3),(w4,w5))
        acc2<false, true>(pk2(CWi[2], CWi[3]), pk2(CWi[4], CWi[5]),
                          pk2(CWt[2], CWt[3]), pk2(CWt[4], CWt[5]),
                          cIa, cIb, cTa, cTb, gxm, gxp, dot[0], den[0]);
        // k1..3: (0,1,dx) carried y+1 row
        row3p<YG>(UWi, UWt, cIa, cIb, cTa, cTb,
                  YG ? gpA0 : gxm, gpB0, YG ? gpB2 : gxp, dot, den, 1);
        // k4..6: (1,-1,dx)
        row3p<YG>(NmI, NmT, cIa, cIb, cTa, cTb,
                  YG ? gmA0 : gxm, gmB0, YG ? gmB2 : gxp, dot, den, 4);
        // k7..9: (1,0,dx)
        row3p<false>(NcI, NcT, cIa, cIb, cTa, cTb, gxm, gmB0, gxp, dot, den, 7);
        // k10..12: (1,1,dx)
        row3p<YG>(NpI, NpT, cIa, cIb, cTa, cTb,
                  YG ? gpA0 : gxm, gpB0, YG ? gpB2 : gxp, dot, den, 10);

#pragma unroll
        for (int j = 0; j < 6; ++j) {
            CWi[j] = NcI[j]; CWt[j] = NcT[j];
            UWi[j] = NpI[j]; UWt[j] = NpT[j];
        }
        base = baseN;
    }

    if (do_epi) {  // z = 127: only dz=0 offsets, no fresh loads
        const u64 cIa = pk2(CWi[1], CWi[2]), cIb = pk2(CWi[3], CWi[4]);
        const u64 cTa = pk2(CWt[1], CWt[2]), cTb = pk2(CWt[3], CWt[4]);
        BCE4(CWi, CWt);
        acc2<false, true>(pk2(CWi[2], CWi[3]), pk2(CWi[4], CWi[5]),
                          pk2(CWt[2], CWt[3]), pk2(CWt[4], CWt[5]),
                          cIa, cIb, cTa, cTb, gxm, gxp, dot[0], den[0]);
        row3p<YG>(UWi, UWt, cIa, cIb, cTa, cTb,
                  YG ? gpA0 : gxm, gpB0, YG ? gpB2 : gxp, dot, den, 1);
    }
}

__global__ void __launch_bounds__(128) gc3d_main_kernel(
    const float* __restrict__ in, const float* __restrict__ tg)
{
    const int tid = blockIdx.x * blockDim.x + threadIdx.x;   // 0..147455
    const int x4 = tid % NX4;
    const int y  = (tid / NX4) % DY;
    const int t2 = tid / (NX4 * DY);   // 0..15
    const int zc = t2 & 3;
    const int b  = t2 >> 2;
    const int z0 = zc * ZSTEP;

    int base = ((b * DZ + z0) * DY + y) * DX + x4 * 4;

    const int   o_m1 = (x4 == 0)       ? 0 : -1;
    const int   o_p4 = (x4 == NX4 - 1) ? 3 : 4;
    const float fxm  = (x4 == 0)       ? 0.0f : 1.0f;
    const float fxp  = (x4 == NX4 - 1) ? 0.0f : 1.0f;
    const int   dUp  = (y == DY - 1) ? 0 : DX;
    const int   dDn  = (y == 0)      ? 0 : -DX;
    const float fyp  = (y == DY - 1) ? 0.0f : 1.0f;
    const float fym  = (y == 0)      ? 0.0f : 1.0f;

    const int  nsteps = (zc == ZCHUNKS - 1) ? (ZSTEP - 1) : ZSTEP;
    const bool do_epi = (zc == ZCHUNKS - 1);

    u64 dot[13], den[13];
    float bce = 0.0f;
#pragma unroll
    for (int k = 0; k < 13; ++k) { dot[k] = 0ULL; den[k] = 0ULL; }

    if (y == 0 || y == DY - 1)
        gc3d_march<true >(in, tg, base, nsteps, do_epi, o_m1, o_p4, dUp, dDn,
                          fxm, fxp, fym, fyp, dot, den, bce);
    else
        gc3d_march<false>(in, tg, base, nsteps, do_epi, o_m1, o_p4, dUp, dDn,
                          fxm, fxp, fym, fyp, dot, den, bce);

    // unpack lanes, warp butterfly, block reduce, atomic into doubles
    float acc[NSUM];
#pragma unroll
    for (int k = 0; k < 13; ++k) {
        float lo, hi;
        upk(dot[k], lo, hi); acc[k]      = lo + hi;
        upk(den[k], lo, hi); acc[13 + k] = lo + hi;
    }
    acc[26] = bce;

#pragma unroll
    for (int i = 0; i < NSUM; ++i) {
        float v = acc[i];
#pragma unroll
        for (int o = 16; o > 0; o >>= 1) v += __shfl_xor_sync(0xFFFFFFFFu, v, o);
        acc[i] = v;
    }

    __shared__ float sh[4][NSUM];
    const int wid = threadIdx.x >> 5;
    const int lid = threadIdx.x & 31;
    if (lid == 0) {
#pragma unroll
        for (int i = 0; i < NSUM; ++i) sh[wid][i] = acc[i];
    }
    __syncthreads();
    if (wid == 0 && lid < NSUM) {
        float v = sh[0][lid] + sh[1][lid] + sh[2][lid] + sh[3][lid];
        atomicAdd(&g_sums[lid], (double)v);
    }
}

__global__ void gc3d_finalize_kernel(float* out, double inv_n) {
    if (threadIdx.x == 0 && blockIdx.x == 0) {
        double accv = 0.0;
#pragma unroll
        for (int k = 0; k < 13; ++k)
            accv += g_sums[k] / (g_sums[13 + k] + 1e-5);
        const double bce = -g_sums[26] * inv_n * 0.6931471805599453; // log2 -> ln
        out[0] = (float)(bce + 1.0 - accv / 13.0);
    }
}

extern "C" void kernel_launch(void* const* d_in, const int* in_sizes, int n_in,
                              void* d_out, int out_size)
{
    const float* in = (const float*)d_in[0];
    const float* tg = (const float*)d_in[1];
    float* out = (float*)d_out;
    const int n = in_sizes[0];   // 18874368

    gc3d_zero_kernel<<<1, 32>>>();
    gc3d_main_kernel<<<1152, 128>>>(in, tg);
    gc3d_finalize_kernel<<<1, 32>>>(out, 1.0 / (double)n);
}